// round 7
// baseline (speedup 1.0000x reference)
#include <cuda_runtime.h>
#include <cuda_bf16.h>
#include <cstdint>

// Problem constants
#define NN   100000
#define RR   3
#define EE   320000
#define HH   4
#define DD   32

// ---------------------------------------------------------------------------
// Scratch (device globals; no runtime allocation)
// ---------------------------------------------------------------------------
__device__ __align__(16) float  g_Wc [RR * 128 * 128];   // folded src weight: Wt_src@Wg
__device__ __align__(16) float  g_bc [RR * 128];         // folded src bias:  bt_src@Wg
__device__ __align__(16) float  g_Vt [RR * HH * 128];    // [r][h][f] dst-side folded vector
__device__ __align__(16) float  g_cc [RR * HH];          // dst-side folded bias
__device__ __align__(16) float  g_hs [(size_t)RR * NN * 128];  // 153.6 MB
__device__ __align__(16) float  g_rst[(size_t)RR * NN * 128];  // 153.6 MB (becomes z)
__device__ float4 g_el  [RR * NN];
__device__ float4 g_er  [RR * NN];
__device__ float4 g_ssum[RR * NN];
__device__ float  g_wsum[RR];
__device__ float  g_a   [RR];

// ---------------------------------------------------------------------------
// Helpers
// ---------------------------------------------------------------------------
__device__ __forceinline__ void red_add_v4(float4* p, float4 v) {
    asm volatile("red.global.add.v4.f32 [%0], {%1,%2,%3,%4};"
                 :: "l"(p), "f"(v.x), "f"(v.y), "f"(v.z), "f"(v.w) : "memory");
}
__device__ __forceinline__ unsigned long long ffma2(unsigned long long a,
                                                    unsigned long long b,
                                                    unsigned long long c) {
    unsigned long long d;
    asm("fma.rn.f32x2 %0, %1, %2, %3;" : "=l"(d) : "l"(a), "l"(b), "l"(c));
    return d;
}
__device__ __forceinline__ unsigned long long dup2(float x) {
    unsigned long long r;
    asm("mov.b64 %0, {%1, %1};" : "=l"(r) : "f"(x));
    return r;
}
__device__ __forceinline__ float2 unpk(unsigned long long v) {
    float2 f;
    asm("mov.b64 {%0, %1}, %2;" : "=f"(f.x), "=f"(f.y) : "l"(v));
    return f;
}
__device__ __forceinline__ float tanh_fast(float x) {
    float y;
    asm("tanh.approx.f32 %0, %1;" : "=f"(y) : "f"(x));
    return y;
}
__device__ __forceinline__ float lrelu(float v) { return v > 0.f ? v : 0.2f * v; }

// ---------------------------------------------------------------------------
// Kernel 0: zero accumulators
// ---------------------------------------------------------------------------
__global__ void init_kernel() {
    size_t stride = (size_t)gridDim.x * blockDim.x;
    size_t i = (size_t)blockIdx.x * blockDim.x + threadIdx.x;
    float4 z = make_float4(0.f, 0.f, 0.f, 0.f);
    float4* r4 = (float4*)g_rst;
    size_t n4 = (size_t)RR * NN * 32;
    for (size_t j = i; j < n4; j += stride) r4[j] = z;
    for (size_t j = i; j < (size_t)RR * NN; j += stride) g_ssum[j] = z;
    if (i < RR) g_wsum[i] = 0.f;
}

// ---------------------------------------------------------------------------
// Kernel 1: Wc[r] = Wt_src[r] @ Wg[r],  bc[r] = bt_src[r] @ Wg[r]
// ---------------------------------------------------------------------------
__global__ __launch_bounds__(256) void prep_wc_kernel(
        const float* __restrict__ Wt_src, const float* __restrict__ Wg,
        const float* __restrict__ bt_src) {
    int r = blockIdx.x;
    const float* Wt  = Wt_src + r * 128 * 128;
    const float* Wgr = Wg     + r * 128 * 128;
    __shared__ float Wgs[32][128];
    int tid = threadIdx.x;
    int lane = tid & 31;
    int f0 = (tid >> 5) * 16;
    float acc[16][4] = {};
    for (int kk = 0; kk < 128; kk += 32) {
        for (int idx = tid; idx < 32 * 128; idx += 256)
            Wgs[idx >> 7][idx & 127] = Wgr[(kk + (idx >> 7)) * 128 + (idx & 127)];
        __syncthreads();
        for (int k = 0; k < 32; k++) {
            float4 w = *(const float4*)&Wgs[k][lane * 4];
            #pragma unroll
            for (int i = 0; i < 16; i++) {
                float x = __ldg(&Wt[(f0 + i) * 128 + kk + k]);
                acc[i][0] += x * w.x; acc[i][1] += x * w.y;
                acc[i][2] += x * w.z; acc[i][3] += x * w.w;
            }
        }
        __syncthreads();
    }
    #pragma unroll
    for (int i = 0; i < 16; i++)
        *(float4*)&g_Wc[(r * 128 + f0 + i) * 128 + lane * 4] =
            make_float4(acc[i][0], acc[i][1], acc[i][2], acc[i][3]);
    if (tid < 128) {
        float s = 0.f;
        for (int k = 0; k < 128; k++) s += bt_src[r * 128 + k] * Wgr[k * 128 + tid];
        g_bc[r * 128 + tid] = s;
    }
}

// ---------------------------------------------------------------------------
// Kernel 2: dst-side fold (Vt, cc)
// ---------------------------------------------------------------------------
__global__ void prep_v_kernel(const float* __restrict__ Wt_dst,
                              const float* __restrict__ bt_dst,
                              const float* __restrict__ Wg,
                              const float* __restrict__ attn_r) {
    int r = blockIdx.x;
    __shared__ float P[128][4];
    int tid = threadIdx.x;   // 128 threads
    const float* Wgr = Wg + r * 128 * 128;
    #pragma unroll
    for (int h = 0; h < 4; h++) {
        float s = 0.f;
        for (int d = 0; d < 32; d++)
            s += Wgr[tid * 128 + h * 32 + d] * attn_r[(r * 4 + h) * 32 + d];
        P[tid][h] = s;
    }
    __syncthreads();
    float v0 = 0.f, v1 = 0.f, v2 = 0.f, v3 = 0.f;
    for (int k = 0; k < 128; k++) {
        float wt = Wt_dst[tid * 128 + k];
        v0 += wt * P[k][0]; v1 += wt * P[k][1];
        v2 += wt * P[k][2]; v3 += wt * P[k][3];
    }
    g_Vt[(r * 4 + 0) * 128 + tid] = v0;
    g_Vt[(r * 4 + 1) * 128 + tid] = v1;
    g_Vt[(r * 4 + 2) * 128 + tid] = v2;
    g_Vt[(r * 4 + 3) * 128 + tid] = v3;
    if (tid < 4) {
        float s = 0.f;
        for (int k = 0; k < 128; k++) s += bt_dst[k] * P[k][tid];
        g_cc[r * 4 + tid] = s;
    }
}

// ---------------------------------------------------------------------------
// Kernel 3: hs[r] = src_feats[r] @ Wc[r] + bc[r]  — FFMA2 128x128 tile,
//           8x8 per thread, row-pair packed accumulators; el epilogue fused.
// ---------------------------------------------------------------------------
__global__ __launch_bounds__(256) void hs_gemm_kernel(
        const float* __restrict__ src_feats, const float* __restrict__ attn_l) {
    int r = blockIdx.y;
    int row0 = blockIdx.x * 128;
    __shared__ __align__(16) float Xs[32][128];   // [k][row] transposed
    __shared__ __align__(16) float Ws[32][128];   // [k][col]
    int tid = threadIdx.x;
    int tx = tid & 15, ty = tid >> 4;             // cols tx+16j, rows ty*8..+7
    const float* X = src_feats + (size_t)r * NN * 128;
    const float* W = g_Wc + r * 128 * 128;
    unsigned long long acc[4][8] = {};
    int rowL = tid & 127;
    int c0 = tid >> 7;      // 0/1
    int g4 = tid & 31;
    int k0 = tid >> 5;      // 0..7
    for (int kk = 0; kk < 128; kk += 32) {
        int grow = row0 + rowL;
        #pragma unroll
        for (int it = 0; it < 4; it++) {
            int c = c0 + it * 2;
            float4 v = make_float4(0.f, 0.f, 0.f, 0.f);
            if (grow < NN) v = *(const float4*)&X[(size_t)grow * 128 + kk + c * 4];
            Xs[c * 4 + 0][rowL] = v.x; Xs[c * 4 + 1][rowL] = v.y;
            Xs[c * 4 + 2][rowL] = v.z; Xs[c * 4 + 3][rowL] = v.w;
        }
        #pragma unroll
        for (int it = 0; it < 4; it++) {
            int k = k0 + it * 8;
            *(float4*)&Ws[k][g4 * 4] = *(const float4*)&W[(kk + k) * 128 + g4 * 4];
        }
        __syncthreads();
        #pragma unroll 8
        for (int k = 0; k < 32; k++) {
            ulonglong2 xa = *(const ulonglong2*)&Xs[k][ty * 8];
            ulonglong2 xb = *(const ulonglong2*)&Xs[k][ty * 8 + 4];
            #pragma unroll
            for (int j = 0; j < 8; j++) {
                unsigned long long wd = dup2(Ws[k][tx + 16 * j]);
                acc[0][j] = ffma2(xa.x, wd, acc[0][j]);
                acc[1][j] = ffma2(xa.y, wd, acc[1][j]);
                acc[2][j] = ffma2(xb.x, wd, acc[2][j]);
                acc[3][j] = ffma2(xb.y, wd, acc[3][j]);
            }
        }
        __syncthreads();
    }
    float bcl[8], all[8];
    #pragma unroll
    for (int j = 0; j < 8; j++) {
        bcl[j] = __ldg(&g_bc[r * 128 + tx + 16 * j]);
        all[j] = __ldg(&attn_l[r * 128 + tx + 16 * j]);  // col = h*32+d flattening
    }
    #pragma unroll
    for (int rp = 0; rp < 4; rp++) {
        float2 u[8];
        #pragma unroll
        for (int j = 0; j < 8; j++) u[j] = unpk(acc[rp][j]);
        #pragma unroll
        for (int half = 0; half < 2; half++) {
            int row = row0 + ty * 8 + rp * 2 + half;
            float v[8];
            #pragma unroll
            for (int j = 0; j < 8; j++) v[j] = (half ? u[j].y : u[j].x) + bcl[j];
            float ph[4];
            #pragma unroll
            for (int h = 0; h < 4; h++) {     // head of col tx+16j is j>>1
                float p = v[2 * h] * all[2 * h] + v[2 * h + 1] * all[2 * h + 1];
                p += __shfl_xor_sync(0xffffffffu, p, 1, 16);
                p += __shfl_xor_sync(0xffffffffu, p, 2, 16);
                p += __shfl_xor_sync(0xffffffffu, p, 4, 16);
                p += __shfl_xor_sync(0xffffffffu, p, 8, 16);
                ph[h] = p;
            }
            if (row < NN) {
                float* dst = &g_hs[((size_t)r * NN + row) * 128];
                #pragma unroll
                for (int j = 0; j < 8; j++) dst[tx + 16 * j] = v[j];
                if (tx == 0)
                    g_el[(size_t)r * NN + row] = make_float4(ph[0], ph[1], ph[2], ph[3]);
            }
        }
    }
}

// ---------------------------------------------------------------------------
// Kernel 4: er[r][n][h] = dst_feat[n] . Vt[r][h] + cc[r][h]   (warp per node)
// ---------------------------------------------------------------------------
__global__ __launch_bounds__(256) void er_kernel(const float* __restrict__ dst_feat) {
    int node = (int)((blockIdx.x * (size_t)blockDim.x + threadIdx.x) >> 5);
    int lane = threadIdx.x & 31;
    if (node >= NN) return;
    float4 xv = *(const float4*)&dst_feat[(size_t)node * 128 + lane * 4];
    float p[12];
    #pragma unroll
    for (int rh = 0; rh < 12; rh++) {
        float4 v = *(const float4*)&g_Vt[rh * 128 + lane * 4];
        p[rh] = xv.x * v.x + xv.y * v.y + xv.z * v.z + xv.w * v.w;
    }
    #pragma unroll
    for (int rh = 0; rh < 12; rh++) {
        #pragma unroll
        for (int off = 16; off; off >>= 1)
            p[rh] += __shfl_xor_sync(0xffffffffu, p[rh], off);
    }
    if (lane == 0) {
        #pragma unroll
        for (int r = 0; r < RR; r++)
            g_er[r * NN + node] = make_float4(
                p[r * 4 + 0] + g_cc[r * 4 + 0], p[r * 4 + 1] + g_cc[r * 4 + 1],
                p[r * 4 + 2] + g_cc[r * 4 + 2], p[r * 4 + 3] + g_cc[r * 4 + 3]);
    }
}

// ---------------------------------------------------------------------------
// Kernel 5: per edge, one relation: ssum[d] += exp(leaky(el[s]+er[d]))
// ---------------------------------------------------------------------------
__global__ __launch_bounds__(256) void edge_pass1(const int* __restrict__ sidx,
                                                  const int* __restrict__ didx, int r) {
    int e = blockIdx.x * 256 + threadIdx.x;
    if (e >= EE) return;
    int s = __ldg(&sidx[r * EE + e]);
    int d = __ldg(&didx[r * EE + e]);
    float4 el = g_el[(size_t)r * NN + s];
    float4 er = g_er[(size_t)r * NN + d];
    float4 ex = make_float4(expf(lrelu(el.x + er.x)), expf(lrelu(el.y + er.y)),
                            expf(lrelu(el.z + er.z)), expf(lrelu(el.w + er.w)));
    red_add_v4(&g_ssum[(size_t)r * NN + d], ex);
}

// ---------------------------------------------------------------------------
// Kernel 6: per edge, one relation: rst[d] += alpha * hs[s]  (warp/edge, red.v4)
// exp recomputed (bitwise-identical to pass1) — no g_ex traffic.
// ---------------------------------------------------------------------------
__global__ __launch_bounds__(256) void edge_pass2(const int* __restrict__ sidx,
                                                  const int* __restrict__ didx, int r) {
    int e = blockIdx.x * 8 + (threadIdx.x >> 5);
    if (e >= EE) return;
    int lane = threadIdx.x & 31;
    int s = __ldg(&sidx[r * EE + e]);
    int d = __ldg(&didx[r * EE + e]);
    const float* elp = (const float*)&g_el[(size_t)r * NN + s];
    const float* erp = (const float*)&g_er[(size_t)r * NN + d];
    const float* ssp = (const float*)&g_ssum[(size_t)r * NN + d];
    int h = lane >> 3;
    float v = lrelu(elp[h] + erp[h]);
    float alpha = expf(v) / (ssp[h] + 1e-9f);
    float4 hv = *(const float4*)&g_hs[((size_t)r * NN + s) * 128 + lane * 4];
    red_add_v4((float4*)&g_rst[((size_t)r * NN + d) * 128 + lane * 4],
               make_float4(alpha * hv.x, alpha * hv.y, alpha * hv.z, alpha * hv.w));
}

// ---------------------------------------------------------------------------
// Kernel 7: z = elu(rst+bias_g) in place; fused semantic GEMM (FFMA2) +
//           logit reduction wsum[r] += sum_n tanh(z@W1+b1)@W2
// ---------------------------------------------------------------------------
__global__ __launch_bounds__(256) void finalize_kernel(
        const float* __restrict__ bias_g, const float* __restrict__ W1,
        const float* __restrict__ b1, const float* __restrict__ W2) {
    int r = blockIdx.y;
    int row0 = blockIdx.x * 128;
    __shared__ __align__(16) float Xs[32][128];
    __shared__ __align__(16) float Ws[32][128];
    __shared__ float wsums[8];
    int tid = threadIdx.x;
    int tx = tid & 15, ty = tid >> 4;
    float* rst = g_rst + (size_t)r * NN * 128;
    unsigned long long acc[4][8] = {};
    int rowL = tid & 127;
    int c0 = tid >> 7;
    int g4 = tid & 31;
    int k0 = tid >> 5;
    for (int kk = 0; kk < 128; kk += 32) {
        int grow = row0 + rowL;
        #pragma unroll
        for (int it = 0; it < 4; it++) {
            int c = c0 + it * 2;
            float4 z = make_float4(0.f, 0.f, 0.f, 0.f);
            if (grow < NN) {
                size_t off = (size_t)grow * 128 + kk + c * 4;
                float4 v = *(const float4*)&rst[off];
                float4 b = *(const float4*)&bias_g[r * 128 + kk + c * 4];
                float a0 = v.x + b.x, a1 = v.y + b.y, a2 = v.z + b.z, a3 = v.w + b.w;
                z.x = a0 > 0.f ? a0 : expm1f(a0);
                z.y = a1 > 0.f ? a1 : expm1f(a1);
                z.z = a2 > 0.f ? a2 : expm1f(a2);
                z.w = a3 > 0.f ? a3 : expm1f(a3);
                *(float4*)&rst[off] = z;             // rst becomes z_r
            }
            Xs[c * 4 + 0][rowL] = z.x; Xs[c * 4 + 1][rowL] = z.y;
            Xs[c * 4 + 2][rowL] = z.z; Xs[c * 4 + 3][rowL] = z.w;
        }
        #pragma unroll
        for (int it = 0; it < 4; it++) {
            int k = k0 + it * 8;
            *(float4*)&Ws[k][g4 * 4] = *(const float4*)&W1[(kk + k) * 128 + g4 * 4];
        }
        __syncthreads();
        #pragma unroll 8
        for (int k = 0; k < 32; k++) {
            ulonglong2 xa = *(const ulonglong2*)&Xs[k][ty * 8];
            ulonglong2 xb = *(const ulonglong2*)&Xs[k][ty * 8 + 4];
            #pragma unroll
            for (int j = 0; j < 8; j++) {
                unsigned long long wd = dup2(Ws[k][tx + 16 * j]);
                acc[0][j] = ffma2(xa.x, wd, acc[0][j]);
                acc[1][j] = ffma2(xa.y, wd, acc[1][j]);
                acc[2][j] = ffma2(xb.x, wd, acc[2][j]);
                acc[3][j] = ffma2(xb.y, wd, acc[3][j]);
            }
        }
        __syncthreads();
    }
    float b1l[8], w2l[8];
    #pragma unroll
    for (int j = 0; j < 8; j++) {
        b1l[j] = __ldg(&b1[tx + 16 * j]);
        w2l[j] = __ldg(&W2[tx + 16 * j]);
    }
    float tot = 0.f;
    #pragma unroll
    for (int rp = 0; rp < 4; rp++) {
        float2 u[8];
        #pragma unroll
        for (int j = 0; j < 8; j++) u[j] = unpk(acc[rp][j]);
        #pragma unroll
        for (int half = 0; half < 2; half++) {
            int row = row0 + ty * 8 + rp * 2 + half;
            float p = 0.f;
            #pragma unroll
            for (int j = 0; j < 8; j++) {
                float v = (half ? u[j].y : u[j].x) + b1l[j];
                p += tanh_fast(v) * w2l[j];
            }
            p += __shfl_xor_sync(0xffffffffu, p, 1, 16);
            p += __shfl_xor_sync(0xffffffffu, p, 2, 16);
            p += __shfl_xor_sync(0xffffffffu, p, 4, 16);
            p += __shfl_xor_sync(0xffffffffu, p, 8, 16);
            if (row < NN) tot += p;   // uniform within half-warp
        }
    }
    tot += __shfl_xor_sync(0xffffffffu, tot, 16);
    if ((tid & 31) == 0) wsums[tid >> 5] = tot;
    __syncthreads();
    if (tid == 0) {
        float s = 0.f;
        #pragma unroll
        for (int i = 0; i < 8; i++) s += wsums[i];
        atomicAdd(&g_wsum[r], s);
    }
}

// ---------------------------------------------------------------------------
// Kernel 8: semantic softmax; write att_mp tail
// ---------------------------------------------------------------------------
__global__ void softmax_kernel(float* __restrict__ out) {
    if (threadIdx.x == 0) {
        float v[RR], m = -1e30f;
        for (int r = 0; r < RR; r++) { v[r] = g_wsum[r] / (float)NN; m = fmaxf(m, v[r]); }
        float s = 0.f;
        for (int r = 0; r < RR; r++) { v[r] = expf(v[r] - m); s += v[r]; }
        for (int r = 0; r < RR; r++) {
            float a = v[r] / s;
            g_a[r] = a;
            out[(size_t)NN * 128 + r] = a;
        }
    }
}

// ---------------------------------------------------------------------------
// Kernel 9: z = sum_r a[r] * z_r
// ---------------------------------------------------------------------------
__global__ void combine_kernel(float* __restrict__ out) {
    size_t stride = (size_t)gridDim.x * blockDim.x;
    size_t i = (size_t)blockIdx.x * blockDim.x + threadIdx.x;
    float a0 = g_a[0], a1 = g_a[1], a2 = g_a[2];
    const float4* r0 = (const float4*)g_rst;
    const float4* r1 = r0 + (size_t)NN * 32;
    const float4* r2 = r1 + (size_t)NN * 32;
    float4* o = (float4*)out;
    size_t n4 = (size_t)NN * 32;
    for (size_t j = i; j < n4; j += stride) {
        float4 x0 = r0[j], x1 = r1[j], x2 = r2[j];
        o[j] = make_float4(a0 * x0.x + a1 * x1.x + a2 * x2.x,
                           a0 * x0.y + a1 * x1.y + a2 * x2.y,
                           a0 * x0.z + a1 * x1.z + a2 * x2.z,
                           a0 * x0.w + a1 * x1.w + a2 * x2.w);
    }
}

// ---------------------------------------------------------------------------
// Launch
// ---------------------------------------------------------------------------
extern "C" void kernel_launch(void* const* d_in, const int* in_sizes, int n_in,
                              void* d_out, int out_size) {
    const float* dst_feat  = (const float*)d_in[0];
    const float* src_feats = (const float*)d_in[1];
    const int*   src_idx   = (const int*)  d_in[2];
    const int*   dst_idx   = (const int*)  d_in[3];
    const float* Wt_dst    = (const float*)d_in[4];
    const float* bt_dst    = (const float*)d_in[5];
    const float* Wt_src    = (const float*)d_in[6];
    const float* bt_src    = (const float*)d_in[7];
    const float* Wg        = (const float*)d_in[8];
    const float* attn_l    = (const float*)d_in[9];
    const float* attn_r    = (const float*)d_in[10];
    const float* bias_g    = (const float*)d_in[11];
    const float* W1        = (const float*)d_in[12];
    const float* b1        = (const float*)d_in[13];
    const float* W2        = (const float*)d_in[14];
    float* out = (float*)d_out;

    const int rowBlocks = (NN + 127) / 128;   // 782

    init_kernel<<<2048, 256>>>();
    prep_wc_kernel<<<RR, 256>>>(Wt_src, Wg, bt_src);
    prep_v_kernel<<<RR, 128>>>(Wt_dst, bt_dst, Wg, attn_r);
    hs_gemm_kernel<<<dim3(rowBlocks, RR), 256>>>(src_feats, attn_l);
    er_kernel<<<(NN + 7) / 8, 256>>>(dst_feat);
    // per-relation edge passes: working set (hs_r + rst_r + ssum_r) ~ fits L2.
    // r=2's hs tile is the most recently written -> process it first.
    for (int r = RR - 1; r >= 0; r--) {
        edge_pass1<<<(EE + 255) / 256, 256>>>(src_idx, dst_idx, r);
        edge_pass2<<<(EE + 7) / 8, 256>>>(src_idx, dst_idx, r);
    }
    finalize_kernel<<<dim3(rowBlocks, RR), 256>>>(bias_g, W1, b1, W2);
    softmax_kernel<<<1, 32>>>(out);
    combine_kernel<<<2048, 256>>>(out);
}

// round 8
// speedup vs baseline: 1.3202x; 1.3202x over previous
#include <cuda_runtime.h>
#include <cuda_bf16.h>
#include <cstdint>

// Problem constants
#define NN   100000
#define RR   3
#define EE   320000
#define HH   4
#define DD   32
#define NTOT (RR * NN)
#define ETOT (RR * EE)
#define CH   2048
#define NCHUNK ((NTOT + CH - 1) / CH)   // 147

// ---------------------------------------------------------------------------
// Scratch (device globals; no runtime allocation)
// ---------------------------------------------------------------------------
__device__ __align__(16) float  g_Wc [RR * 128 * 128];
__device__ __align__(16) float  g_bc [RR * 128];
__device__ __align__(16) float  g_Vt [RR * HH * 128];
__device__ __align__(16) float  g_cc [RR * HH];
__device__ __align__(16) float  g_hs [(size_t)RR * NN * 128];  // 153.6 MB
__device__ __align__(16) float  g_z  [(size_t)RR * NN * 128];  // 153.6 MB
__device__ float4 g_el  [RR * NN];
__device__ float4 g_er  [RR * NN];
__device__ float  g_wsum[RR];
__device__ float  g_a   [RR];
// CSR scratch
__device__ int g_deg   [NTOT];
__device__ int g_rowptr[NTOT + 1];
__device__ int g_cur   [NTOT];
__device__ int g_csum  [NCHUNK];
__device__ int g_coff  [NCHUNK];
__device__ int g_col   [ETOT];

// ---------------------------------------------------------------------------
// Helpers
// ---------------------------------------------------------------------------
__device__ __forceinline__ unsigned long long ffma2(unsigned long long a,
                                                    unsigned long long b,
                                                    unsigned long long c) {
    unsigned long long d;
    asm("fma.rn.f32x2 %0, %1, %2, %3;" : "=l"(d) : "l"(a), "l"(b), "l"(c));
    return d;
}
__device__ __forceinline__ unsigned long long dup2(float x) {
    unsigned long long r;
    asm("mov.b64 %0, {%1, %1};" : "=l"(r) : "f"(x));
    return r;
}
__device__ __forceinline__ float2 unpk(unsigned long long v) {
    float2 f;
    asm("mov.b64 {%0, %1}, %2;" : "=f"(f.x), "=f"(f.y) : "l"(v));
    return f;
}
__device__ __forceinline__ float tanh_fast(float x) {
    float y;
    asm("tanh.approx.f32 %0, %1;" : "=f"(y) : "f"(x));
    return y;
}
__device__ __forceinline__ float lrelu(float v) { return v > 0.f ? v : 0.2f * v; }

// ---------------------------------------------------------------------------
// CSR build
// ---------------------------------------------------------------------------
__global__ void csr_zero() {
    int i = blockIdx.x * blockDim.x + threadIdx.x;
    if (i < NTOT) g_deg[i] = 0;
    if (i < RR) g_wsum[i] = 0.f;
}
__global__ void csr_hist(const int* __restrict__ didx) {
    int i = blockIdx.x * blockDim.x + threadIdx.x;
    if (i >= ETOT) return;
    int r = i / EE;
    atomicAdd(&g_deg[r * NN + __ldg(&didx[i])], 1);
}
// exclusive scan, phase 1: per-2048 chunk local scan + chunk totals
__global__ __launch_bounds__(256) void scan1() {
    int b = blockIdx.x, tid = threadIdx.x;
    int base = b * CH + tid * 8;
    __shared__ int wtot[8];
    int vals[8], tsum = 0;
    #pragma unroll
    for (int i = 0; i < 8; i++) {
        int idx = base + i;
        int v = (idx < NTOT) ? g_deg[idx] : 0;
        vals[i] = tsum; tsum += v;
    }
    int lane = tid & 31, w = tid >> 5;
    int x = tsum;
    #pragma unroll
    for (int off = 1; off < 32; off <<= 1) {
        int y = __shfl_up_sync(0xffffffffu, x, off);
        if (lane >= off) x += y;
    }
    if (lane == 31) wtot[w] = x;
    __syncthreads();
    if (tid == 0) {
        int run = 0;
        #pragma unroll
        for (int j = 0; j < 8; j++) { int t = wtot[j]; wtot[j] = run; run += t; }
        g_csum[b] = run;
    }
    __syncthreads();
    int texcl = wtot[w] + (x - tsum);
    #pragma unroll
    for (int i = 0; i < 8; i++) {
        int idx = base + i;
        if (idx < NTOT) g_rowptr[idx] = texcl + vals[i];
    }
}
// phase 2: scan chunk totals (NCHUNK <= 256)
__global__ __launch_bounds__(256) void scan2() {
    int tid = threadIdx.x;
    __shared__ int wtot[8];
    int v = (tid < NCHUNK) ? g_csum[tid] : 0;
    int lane = tid & 31, w = tid >> 5;
    int x = v;
    #pragma unroll
    for (int off = 1; off < 32; off <<= 1) {
        int y = __shfl_up_sync(0xffffffffu, x, off);
        if (lane >= off) x += y;
    }
    if (lane == 31) wtot[w] = x;
    __syncthreads();
    if (tid == 0) {
        int run = 0;
        #pragma unroll
        for (int j = 0; j < 8; j++) { int t = wtot[j]; wtot[j] = run; run += t; }
    }
    __syncthreads();
    if (tid < NCHUNK) g_coff[tid] = wtot[w] + (x - v);
    if (tid == 0) g_rowptr[NTOT] = ETOT;
}
// phase 3: add chunk offsets; init cursor
__global__ void scan3() {
    int i = blockIdx.x * blockDim.x + threadIdx.x;
    if (i >= NTOT) return;
    int v = g_rowptr[i] + g_coff[i / CH];
    g_rowptr[i] = v;
    g_cur[i] = v;
}
__global__ void csr_scatter(const int* __restrict__ sidx, const int* __restrict__ didx) {
    int i = blockIdx.x * blockDim.x + threadIdx.x;
    if (i >= ETOT) return;
    int r = i / EE;
    int d = __ldg(&didx[i]);
    int pos = atomicAdd(&g_cur[r * NN + d], 1);
    g_col[pos] = __ldg(&sidx[i]);
}

// ---------------------------------------------------------------------------
// Kernel 1: Wc[r] = Wt_src[r] @ Wg[r],  bc[r] = bt_src[r] @ Wg[r]
// ---------------------------------------------------------------------------
__global__ __launch_bounds__(256) void prep_wc_kernel(
        const float* __restrict__ Wt_src, const float* __restrict__ Wg,
        const float* __restrict__ bt_src) {
    int r = blockIdx.x;
    const float* Wt  = Wt_src + r * 128 * 128;
    const float* Wgr = Wg     + r * 128 * 128;
    __shared__ float Wgs[32][128];
    int tid = threadIdx.x;
    int lane = tid & 31;
    int f0 = (tid >> 5) * 16;
    float acc[16][4] = {};
    for (int kk = 0; kk < 128; kk += 32) {
        for (int idx = tid; idx < 32 * 128; idx += 256)
            Wgs[idx >> 7][idx & 127] = Wgr[(kk + (idx >> 7)) * 128 + (idx & 127)];
        __syncthreads();
        for (int k = 0; k < 32; k++) {
            float4 w = *(const float4*)&Wgs[k][lane * 4];
            #pragma unroll
            for (int i = 0; i < 16; i++) {
                float x = __ldg(&Wt[(f0 + i) * 128 + kk + k]);
                acc[i][0] += x * w.x; acc[i][1] += x * w.y;
                acc[i][2] += x * w.z; acc[i][3] += x * w.w;
            }
        }
        __syncthreads();
    }
    #pragma unroll
    for (int i = 0; i < 16; i++)
        *(float4*)&g_Wc[(r * 128 + f0 + i) * 128 + lane * 4] =
            make_float4(acc[i][0], acc[i][1], acc[i][2], acc[i][3]);
    if (tid < 128) {
        float s = 0.f;
        for (int k = 0; k < 128; k++) s += bt_src[r * 128 + k] * Wgr[k * 128 + tid];
        g_bc[r * 128 + tid] = s;
    }
}

// ---------------------------------------------------------------------------
// Kernel 2: dst-side fold (Vt, cc)
// ---------------------------------------------------------------------------
__global__ void prep_v_kernel(const float* __restrict__ Wt_dst,
                              const float* __restrict__ bt_dst,
                              const float* __restrict__ Wg,
                              const float* __restrict__ attn_r) {
    int r = blockIdx.x;
    __shared__ float P[128][4];
    int tid = threadIdx.x;   // 128 threads
    const float* Wgr = Wg + r * 128 * 128;
    #pragma unroll
    for (int h = 0; h < 4; h++) {
        float s = 0.f;
        for (int d = 0; d < 32; d++)
            s += Wgr[tid * 128 + h * 32 + d] * attn_r[(r * 4 + h) * 32 + d];
        P[tid][h] = s;
    }
    __syncthreads();
    float v0 = 0.f, v1 = 0.f, v2 = 0.f, v3 = 0.f;
    for (int k = 0; k < 128; k++) {
        float wt = Wt_dst[tid * 128 + k];
        v0 += wt * P[k][0]; v1 += wt * P[k][1];
        v2 += wt * P[k][2]; v3 += wt * P[k][3];
    }
    g_Vt[(r * 4 + 0) * 128 + tid] = v0;
    g_Vt[(r * 4 + 1) * 128 + tid] = v1;
    g_Vt[(r * 4 + 2) * 128 + tid] = v2;
    g_Vt[(r * 4 + 3) * 128 + tid] = v3;
    if (tid < 4) {
        float s = 0.f;
        for (int k = 0; k < 128; k++) s += bt_dst[k] * P[k][tid];
        g_cc[r * 4 + tid] = s;
    }
}

// ---------------------------------------------------------------------------
// Kernel 3: hs[r] = src_feats[r] @ Wc[r] + bc[r]  — FFMA2, el fused (per r)
// ---------------------------------------------------------------------------
__global__ __launch_bounds__(256) void hs_gemm_kernel(
        const float* __restrict__ src_feats, const float* __restrict__ attn_l, int r) {
    int row0 = blockIdx.x * 128;
    __shared__ __align__(16) float Xs[32][128];   // [k][row] transposed
    __shared__ __align__(16) float Ws[32][128];   // [k][col]
    int tid = threadIdx.x;
    int tx = tid & 15, ty = tid >> 4;
    const float* X = src_feats + (size_t)r * NN * 128;
    const float* W = g_Wc + r * 128 * 128;
    unsigned long long acc[4][8] = {};
    int rowL = tid & 127;
    int c0 = tid >> 7;
    int g4 = tid & 31;
    int k0 = tid >> 5;
    for (int kk = 0; kk < 128; kk += 32) {
        int grow = row0 + rowL;
        #pragma unroll
        for (int it = 0; it < 4; it++) {
            int c = c0 + it * 2;
            float4 v = make_float4(0.f, 0.f, 0.f, 0.f);
            if (grow < NN) v = *(const float4*)&X[(size_t)grow * 128 + kk + c * 4];
            Xs[c * 4 + 0][rowL] = v.x; Xs[c * 4 + 1][rowL] = v.y;
            Xs[c * 4 + 2][rowL] = v.z; Xs[c * 4 + 3][rowL] = v.w;
        }
        #pragma unroll
        for (int it = 0; it < 4; it++) {
            int k = k0 + it * 8;
            *(float4*)&Ws[k][g4 * 4] = *(const float4*)&W[(kk + k) * 128 + g4 * 4];
        }
        __syncthreads();
        #pragma unroll 8
        for (int k = 0; k < 32; k++) {
            ulonglong2 xa = *(const ulonglong2*)&Xs[k][ty * 8];
            ulonglong2 xb = *(const ulonglong2*)&Xs[k][ty * 8 + 4];
            #pragma unroll
            for (int j = 0; j < 8; j++) {
                unsigned long long wd = dup2(Ws[k][tx + 16 * j]);
                acc[0][j] = ffma2(xa.x, wd, acc[0][j]);
                acc[1][j] = ffma2(xa.y, wd, acc[1][j]);
                acc[2][j] = ffma2(xb.x, wd, acc[2][j]);
                acc[3][j] = ffma2(xb.y, wd, acc[3][j]);
            }
        }
        __syncthreads();
    }
    float bcl[8], all[8];
    #pragma unroll
    for (int j = 0; j < 8; j++) {
        bcl[j] = __ldg(&g_bc[r * 128 + tx + 16 * j]);
        all[j] = __ldg(&attn_l[r * 128 + tx + 16 * j]);  // col = h*32+d flattening
    }
    #pragma unroll
    for (int rp = 0; rp < 4; rp++) {
        float2 u[8];
        #pragma unroll
        for (int j = 0; j < 8; j++) u[j] = unpk(acc[rp][j]);
        #pragma unroll
        for (int half = 0; half < 2; half++) {
            int row = row0 + ty * 8 + rp * 2 + half;
            float v[8];
            #pragma unroll
            for (int j = 0; j < 8; j++) v[j] = (half ? u[j].y : u[j].x) + bcl[j];
            float ph[4];
            #pragma unroll
            for (int h = 0; h < 4; h++) {
                float p = v[2 * h] * all[2 * h] + v[2 * h + 1] * all[2 * h + 1];
                p += __shfl_xor_sync(0xffffffffu, p, 1, 16);
                p += __shfl_xor_sync(0xffffffffu, p, 2, 16);
                p += __shfl_xor_sync(0xffffffffu, p, 4, 16);
                p += __shfl_xor_sync(0xffffffffu, p, 8, 16);
                ph[h] = p;
            }
            if (row < NN) {
                float* dst = &g_hs[((size_t)r * NN + row) * 128];
                #pragma unroll
                for (int j = 0; j < 8; j++) dst[tx + 16 * j] = v[j];
                if (tx == 0)
                    g_el[(size_t)r * NN + row] = make_float4(ph[0], ph[1], ph[2], ph[3]);
            }
        }
    }
}

// ---------------------------------------------------------------------------
// Kernel 4: er[r][n][h] = dst_feat[n] . Vt[r][h] + cc[r][h]   (warp per node)
// ---------------------------------------------------------------------------
__global__ __launch_bounds__(256) void er_kernel(const float* __restrict__ dst_feat) {
    int node = (int)((blockIdx.x * (size_t)blockDim.x + threadIdx.x) >> 5);
    int lane = threadIdx.x & 31;
    if (node >= NN) return;
    float4 xv = *(const float4*)&dst_feat[(size_t)node * 128 + lane * 4];
    float p[12];
    #pragma unroll
    for (int rh = 0; rh < 12; rh++) {
        float4 v = *(const float4*)&g_Vt[rh * 128 + lane * 4];
        p[rh] = xv.x * v.x + xv.y * v.y + xv.z * v.z + xv.w * v.w;
    }
    #pragma unroll
    for (int rh = 0; rh < 12; rh++) {
        #pragma unroll
        for (int off = 16; off; off >>= 1)
            p[rh] += __shfl_xor_sync(0xffffffffu, p[rh], off);
    }
    if (lane == 0) {
        #pragma unroll
        for (int r = 0; r < RR; r++)
            g_er[r * NN + node] = make_float4(
                p[r * 4 + 0] + g_cc[r * 4 + 0], p[r * 4 + 1] + g_cc[r * 4 + 1],
                p[r * 4 + 2] + g_cc[r * 4 + 2], p[r * 4 + 3] + g_cc[r * 4 + 3]);
    }
}

// ---------------------------------------------------------------------------
// Kernel 5: CSR gather — warp per dst node, single pass:
//   z[d] = elu( (sum_e ex_e * hs[s_e]) / (sum_e ex_e + 1e-9) + bias_g )
// No atomics, no second pass, no zero-init of the output.
// ---------------------------------------------------------------------------
__global__ __launch_bounds__(256) void gather_kernel(const float* __restrict__ bias_g, int r) {
    int n = blockIdx.x * 8 + (threadIdx.x >> 5);
    if (n >= NN) return;
    int lane = threadIdx.x & 31;
    int h = lane >> 3;
    int beg = __ldg(&g_rowptr[r * NN + n]);
    int end = __ldg(&g_rowptr[r * NN + n + 1]);
    float erh = ((const float*)&g_er[(size_t)r * NN + n])[h];
    float ax = 0.f, ay = 0.f, az = 0.f, aw = 0.f, ss = 0.f;
    for (int e = beg; e < end; e++) {
        int s = __ldg(&g_col[e]);
        float elh = __ldg(&((const float*)&g_el[(size_t)r * NN + s])[h]);
        float ex = expf(lrelu(elh + erh));
        float4 hv = *(const float4*)&g_hs[((size_t)r * NN + s) * 128 + lane * 4];
        ax += ex * hv.x; ay += ex * hv.y; az += ex * hv.z; aw += ex * hv.w;
        ss += ex;
    }
    float inv = 1.f / (ss + 1e-9f);
    float4 b = *(const float4*)&bias_g[r * 128 + lane * 4];
    float z0 = ax * inv + b.x, z1 = ay * inv + b.y;
    float z2 = az * inv + b.z, z3 = aw * inv + b.w;
    z0 = z0 > 0.f ? z0 : expm1f(z0);
    z1 = z1 > 0.f ? z1 : expm1f(z1);
    z2 = z2 > 0.f ? z2 : expm1f(z2);
    z3 = z3 > 0.f ? z3 : expm1f(z3);
    *(float4*)&g_z[((size_t)r * NN + n) * 128 + lane * 4] =
        make_float4(z0, z1, z2, z3);
}

// ---------------------------------------------------------------------------
// Kernel 6: semantic GEMM (FFMA2, read-only z) + logit reduction
// ---------------------------------------------------------------------------
__global__ __launch_bounds__(256) void finalize_kernel(
        const float* __restrict__ W1, const float* __restrict__ b1,
        const float* __restrict__ W2) {
    int r = blockIdx.y;
    int row0 = blockIdx.x * 128;
    __shared__ __align__(16) float Xs[32][128];
    __shared__ __align__(16) float Ws[32][128];
    __shared__ float wsums[8];
    int tid = threadIdx.x;
    int tx = tid & 15, ty = tid >> 4;
    const float* zr = g_z + (size_t)r * NN * 128;
    unsigned long long acc[4][8] = {};
    int rowL = tid & 127;
    int c0 = tid >> 7;
    int g4 = tid & 31;
    int k0 = tid >> 5;
    for (int kk = 0; kk < 128; kk += 32) {
        int grow = row0 + rowL;
        #pragma unroll
        for (int it = 0; it < 4; it++) {
            int c = c0 + it * 2;
            float4 z = make_float4(0.f, 0.f, 0.f, 0.f);
            if (grow < NN) z = *(const float4*)&zr[(size_t)grow * 128 + kk + c * 4];
            Xs[c * 4 + 0][rowL] = z.x; Xs[c * 4 + 1][rowL] = z.y;
            Xs[c * 4 + 2][rowL] = z.z; Xs[c * 4 + 3][rowL] = z.w;
        }
        #pragma unroll
        for (int it = 0; it < 4; it++) {
            int k = k0 + it * 8;
            *(float4*)&Ws[k][g4 * 4] = *(const float4*)&W1[(kk + k) * 128 + g4 * 4];
        }
        __syncthreads();
        #pragma unroll 8
        for (int k = 0; k < 32; k++) {
            ulonglong2 xa = *(const ulonglong2*)&Xs[k][ty * 8];
            ulonglong2 xb = *(const ulonglong2*)&Xs[k][ty * 8 + 4];
            #pragma unroll
            for (int j = 0; j < 8; j++) {
                unsigned long long wd = dup2(Ws[k][tx + 16 * j]);
                acc[0][j] = ffma2(xa.x, wd, acc[0][j]);
                acc[1][j] = ffma2(xa.y, wd, acc[1][j]);
                acc[2][j] = ffma2(xb.x, wd, acc[2][j]);
                acc[3][j] = ffma2(xb.y, wd, acc[3][j]);
            }
        }
        __syncthreads();
    }
    float b1l[8], w2l[8];
    #pragma unroll
    for (int j = 0; j < 8; j++) {
        b1l[j] = __ldg(&b1[tx + 16 * j]);
        w2l[j] = __ldg(&W2[tx + 16 * j]);
    }
    float tot = 0.f;
    #pragma unroll
    for (int rp = 0; rp < 4; rp++) {
        float2 u[8];
        #pragma unroll
        for (int j = 0; j < 8; j++) u[j] = unpk(acc[rp][j]);
        #pragma unroll
        for (int half = 0; half < 2; half++) {
            int row = row0 + ty * 8 + rp * 2 + half;
            float p = 0.f;
            #pragma unroll
            for (int j = 0; j < 8; j++) {
                float v = (half ? u[j].y : u[j].x) + b1l[j];
                p += tanh_fast(v) * w2l[j];
            }
            p += __shfl_xor_sync(0xffffffffu, p, 1, 16);
            p += __shfl_xor_sync(0xffffffffu, p, 2, 16);
            p += __shfl_xor_sync(0xffffffffu, p, 4, 16);
            p += __shfl_xor_sync(0xffffffffu, p, 8, 16);
            if (row < NN) tot += p;
        }
    }
    tot += __shfl_xor_sync(0xffffffffu, tot, 16);
    if ((tid & 31) == 0) wsums[tid >> 5] = tot;
    __syncthreads();
    if (tid == 0) {
        float s = 0.f;
        #pragma unroll
        for (int i = 0; i < 8; i++) s += wsums[i];
        atomicAdd(&g_wsum[r], s);
    }
}

// ---------------------------------------------------------------------------
// Kernel 7: semantic softmax; write att_mp tail
// ---------------------------------------------------------------------------
__global__ void softmax_kernel(float* __restrict__ out) {
    if (threadIdx.x == 0) {
        float v[RR], m = -1e30f;
        for (int r = 0; r < RR; r++) { v[r] = g_wsum[r] / (float)NN; m = fmaxf(m, v[r]); }
        float s = 0.f;
        for (int r = 0; r < RR; r++) { v[r] = expf(v[r] - m); s += v[r]; }
        for (int r = 0; r < RR; r++) {
            float a = v[r] / s;
            g_a[r] = a;
            out[(size_t)NN * 128 + r] = a;
        }
    }
}

// ---------------------------------------------------------------------------
// Kernel 8: z_out = sum_r a[r] * z_r
// ---------------------------------------------------------------------------
__global__ void combine_kernel(float* __restrict__ out) {
    size_t stride = (size_t)gridDim.x * blockDim.x;
    size_t i = (size_t)blockIdx.x * blockDim.x + threadIdx.x;
    float a0 = g_a[0], a1 = g_a[1], a2 = g_a[2];
    const float4* r0 = (const float4*)g_z;
    const float4* r1 = r0 + (size_t)NN * 32;
    const float4* r2 = r1 + (size_t)NN * 32;
    float4* o = (float4*)out;
    size_t n4 = (size_t)NN * 32;
    for (size_t j = i; j < n4; j += stride) {
        float4 x0 = r0[j], x1 = r1[j], x2 = r2[j];
        o[j] = make_float4(a0 * x0.x + a1 * x1.x + a2 * x2.x,
                           a0 * x0.y + a1 * x1.y + a2 * x2.y,
                           a0 * x0.z + a1 * x1.z + a2 * x2.z,
                           a0 * x0.w + a1 * x1.w + a2 * x2.w);
    }
}

// ---------------------------------------------------------------------------
// Launch
// ---------------------------------------------------------------------------
extern "C" void kernel_launch(void* const* d_in, const int* in_sizes, int n_in,
                              void* d_out, int out_size) {
    const float* dst_feat  = (const float*)d_in[0];
    const float* src_feats = (const float*)d_in[1];
    const int*   src_idx   = (const int*)  d_in[2];
    const int*   dst_idx   = (const int*)  d_in[3];
    const float* Wt_dst    = (const float*)d_in[4];
    const float* bt_dst    = (const float*)d_in[5];
    const float* Wt_src    = (const float*)d_in[6];
    const float* bt_src    = (const float*)d_in[7];
    const float* Wg        = (const float*)d_in[8];
    const float* attn_l    = (const float*)d_in[9];
    const float* attn_r    = (const float*)d_in[10];
    const float* bias_g    = (const float*)d_in[11];
    const float* W1        = (const float*)d_in[12];
    const float* b1        = (const float*)d_in[13];
    const float* W2        = (const float*)d_in[14];
    float* out = (float*)d_out;

    const int rowBlocks = (NN + 127) / 128;   // 782

    // CSR build (int-only, ~15us)
    csr_zero<<<(NTOT + 255) / 256, 256>>>();
    csr_hist<<<(ETOT + 255) / 256, 256>>>(dst_idx);
    scan1<<<NCHUNK, 256>>>();
    scan2<<<1, 256>>>();
    scan3<<<(NTOT + 255) / 256, 256>>>();
    csr_scatter<<<(ETOT + 255) / 256, 256>>>(src_idx, dst_idx);

    prep_wc_kernel<<<RR, 256>>>(Wt_src, Wg, bt_src);
    prep_v_kernel<<<RR, 128>>>(Wt_dst, bt_dst, Wg, attn_r);
    er_kernel<<<(NN + 7) / 8, 256>>>(dst_feat);

    // Per relation: GEMM then gather (hs_r stays L2-resident for the gather)
    for (int r = 0; r < RR; r++) {
        hs_gemm_kernel<<<rowBlocks, 256>>>(src_feats, attn_l, r);
        gather_kernel<<<(NN + 7) / 8, 256>>>(bias_g, r);
    }

    finalize_kernel<<<dim3(rowBlocks, RR), 256>>>(W1, b1, W2);
    softmax_kernel<<<1, 32>>>(out);
    combine_kernel<<<2048, 256>>>(out);
}